// round 2
// baseline (speedup 1.0000x reference)
#include <cuda_runtime.h>
#include <cuda_bf16.h>
#include <math.h>

#define Bn 32
#define Sn 2048
#define Hn 1024
#define TEMP 0.07f
#define EPSL 1e-8f

// ---------------- device scratch (static, no allocation) ----------------
__device__ float g_wa[Bn * Sn];
__device__ float g_wo[Bn * Sn];
__device__ float g_pa[Bn * 32 * Hn];   // pooling partials aspect
__device__ float g_po[Bn * 32 * Hn];   // pooling partials opinion
__device__ float g_aemb[Bn * Hn];
__device__ float g_oemb[Bn * Hn];
__device__ float g_sin[Bn * 2 * Hn];
__device__ float g_gp[8 * Bn * 1024];  // gemm partials (max: 8 chunks x 32 x 1024)
__device__ float g_ha[Bn * 512];
__device__ float g_ho[Bn * 512];
__device__ float g_hs[Bn * 1024];
__device__ float g_za[Bn * 128];
__device__ float g_zo[Bn * 128];
__device__ float g_zs[Bn * 256];
__device__ float g_inf[1];

// ---------------- kernel 1: softmax weights over S ----------------
// score[b,s] = sum_{c=1..4} logits[b,s,c]; w = softmax over s.
__global__ void k_softmax_w(const float* __restrict__ la,
                            const float* __restrict__ lo,
                            float* __restrict__ wa, float* __restrict__ wo) {
    int b = blockIdx.x;
    const float* L = blockIdx.y ? lo : la;
    float* W = blockIdx.y ? wo : wa;
    __shared__ float sc[Sn];
    __shared__ float red[16];
    int tid = threadIdx.x;           // 256 threads
    int lane = tid & 31, wid = tid >> 5;

    float m = -1e30f;
    for (int s = tid; s < Sn; s += 256) {
        const float* p = L + ((size_t)b * Sn + s) * 5;
        float v = p[1] + p[2] + p[3] + p[4];
        sc[s] = v;
        m = fmaxf(m, v);
    }
    #pragma unroll
    for (int o2 = 16; o2; o2 >>= 1) m = fmaxf(m, __shfl_xor_sync(0xffffffffu, m, o2));
    if (lane == 0) red[wid] = m;
    __syncthreads();
    if (tid == 0) {
        float mm = red[0];
        for (int w = 1; w < 8; w++) mm = fmaxf(mm, red[w]);
        red[8] = mm;
    }
    __syncthreads();
    m = red[8];
    __syncthreads();

    float sum = 0.f;
    for (int s = tid; s < Sn; s += 256) {
        float e = expf(sc[s] - m);
        sc[s] = e;
        sum += e;
    }
    #pragma unroll
    for (int o2 = 16; o2; o2 >>= 1) sum += __shfl_xor_sync(0xffffffffu, sum, o2);
    if (lane == 0) red[wid] = sum;
    __syncthreads();
    if (tid == 0) {
        float ss = 0.f;
        for (int w = 0; w < 8; w++) ss += red[w];
        red[9] = ss;
    }
    __syncthreads();
    float inv = 1.0f / red[9];
    for (int s = tid; s < Sn; s += 256) W[(size_t)b * Sn + s] = sc[s] * inv;
}

// ---------------- kernel 2: pooling partials (the 256MB pass) ----------------
// grid (32 s-chunks, 32 batches), 256 threads, float4 along H. Reads span ONCE,
// produces both aspect & opinion partial pools.
__global__ void k_pool_partial(const float* __restrict__ span,
                               const float* __restrict__ wa,
                               const float* __restrict__ wo,
                               float* __restrict__ pa, float* __restrict__ po) {
    int sc = blockIdx.x, b = blockIdx.y;
    __shared__ float swa[64], swo[64];
    int tid = threadIdx.x;  // 256
    if (tid < 64) swa[tid] = wa[(size_t)b * Sn + sc * 64 + tid];
    else if (tid < 128) { int t = tid - 64; swo[t] = wo[(size_t)b * Sn + sc * 64 + t]; }
    __syncthreads();

    const float4* base = (const float4*)(span + ((size_t)b * Sn + (size_t)sc * 64) * Hn);
    float4 aa = make_float4(0.f, 0.f, 0.f, 0.f);
    float4 oo = make_float4(0.f, 0.f, 0.f, 0.f);
    #pragma unroll 4
    for (int s = 0; s < 64; s++) {
        float4 v = base[(size_t)s * 256 + tid];
        float fa = swa[s], fo = swo[s];
        aa.x += v.x * fa; aa.y += v.y * fa; aa.z += v.z * fa; aa.w += v.w * fa;
        oo.x += v.x * fo; oo.y += v.y * fo; oo.z += v.z * fo; oo.w += v.w * fo;
    }
    size_t off = ((size_t)b * 32 + sc) * Hn + tid * 4;
    *(float4*)(pa + off) = aa;
    *(float4*)(po + off) = oo;
}

// ---------------- kernel 3: reduce partials -> embeddings + concat ----------------
__global__ void k_pool_reduce(const float* __restrict__ pa, const float* __restrict__ po,
                              float* __restrict__ aemb, float* __restrict__ oemb,
                              float* __restrict__ sin_) {
    int idx = blockIdx.x * 256 + threadIdx.x;  // 32768 total
    int b = idx >> 10, h = idx & 1023;
    float sa = 0.f, so = 0.f;
    #pragma unroll 8
    for (int c = 0; c < 32; c++) {
        sa += pa[((size_t)b * 32 + c) * Hn + h];
        so += po[((size_t)b * 32 + c) * Hn + h];
    }
    aemb[idx] = sa;
    oemb[idx] = so;
    sin_[(size_t)b * 2048 + h] = sa;
    sin_[(size_t)b * 2048 + 1024 + h] = so;
}

// ---------------- kernel 4: generic small GEMM, k-split partials ----------------
// out_part[kc, b, j] = sum_{k in chunk} in[b,k] * W[k,j].  K-chunk fixed at 256.
// block (32,32): tx = j within 32-col tile, ty = b.
__global__ void k_gemm_part(const float* __restrict__ in, const float* __restrict__ W,
                            float* __restrict__ part, int K, int N) {
    __shared__ float sin_[32][256];
    int tx = threadIdx.x, ty = threadIdx.y;
    int j = blockIdx.x * 32 + tx;
    int k0 = blockIdx.y * 256;
    int tid = ty * 32 + tx;
    for (int idx = tid; idx < 32 * 256; idx += 1024) {
        int bb = idx >> 8, kk = idx & 255;
        sin_[bb][kk] = in[(size_t)bb * K + k0 + kk];
    }
    __syncthreads();
    float acc = 0.f;
    const float* Wp = W + (size_t)k0 * N + j;
    #pragma unroll 8
    for (int k = 0; k < 256; k++) acc += sin_[ty][k] * Wp[(size_t)k * N];
    part[((size_t)blockIdx.y * 32 + ty) * N + j] = acc;
}

__global__ void k_gemm_combine(const float* __restrict__ part, const float* __restrict__ bias,
                               float* __restrict__ out, int N, int KC, int relu) {
    int idx = blockIdx.x * 256 + threadIdx.x;
    if (idx >= 32 * N) return;
    int b = idx / N, j = idx % N;
    float s = bias[j];
    for (int c = 0; c < KC; c++) s += part[((size_t)c * 32 + b) * N + j];
    if (relu) s = fmaxf(s, 0.f);
    out[idx] = s;
}

// ---------------- kernel 5: InfoNCE (single block, 1024 threads) ----------------
__global__ void k_infonce(const float* __restrict__ za, const float* __restrict__ zo,
                          const int* __restrict__ labels, float* __restrict__ res) {
    __shared__ float a[32][128];     // accessed broadcast (row fixed per warp)
    __shared__ float o[32][129];     // padded: lane-varying row access
    __shared__ int lab[32];
    __shared__ float rowv[32];
    int tid = threadIdx.x;
    int i = tid >> 5, j = tid & 31;  // warp = row i, lane = col j

    for (int idx = tid; idx < 32 * 128; idx += 1024) a[idx >> 7][idx & 127] = za[idx];
    for (int idx = tid; idx < 32 * 128; idx += 1024) o[idx >> 7][idx & 127] = zo[idx];
    if (tid < 32) lab[tid] = labels[tid];
    __syncthreads();

    // row L2 normalization: warp i handles row i
    {
        float sa = 0.f, so = 0.f;
        #pragma unroll
        for (int t = 0; t < 4; t++) {
            float va = a[i][j + 32 * t]; sa += va * va;
            float vo = o[i][j + 32 * t]; so += vo * vo;
        }
        #pragma unroll
        for (int o2 = 16; o2; o2 >>= 1) {
            sa += __shfl_xor_sync(0xffffffffu, sa, o2);
            so += __shfl_xor_sync(0xffffffffu, so, o2);
        }
        float ia = 1.0f / fmaxf(sqrtf(sa), 1e-12f);
        float io = 1.0f / fmaxf(sqrtf(so), 1e-12f);
        #pragma unroll
        for (int t = 0; t < 4; t++) {
            a[i][j + 32 * t] *= ia;
            o[i][j + 32 * t] *= io;
        }
    }
    __syncthreads();

    float d = 0.f;
    #pragma unroll 8
    for (int k = 0; k < 128; k++) d += a[i][k] * o[j][k];
    float e = expf(d * (1.0f / TEMP));
    bool same = (lab[i] == lab[j]);
    float pm = (i == j) ? 1.0f : (same ? 0.5f : 0.0f);
    float num = e * pm, den = e;
    #pragma unroll
    for (int o2 = 16; o2; o2 >>= 1) {
        num += __shfl_xor_sync(0xffffffffu, num, o2);
        den += __shfl_xor_sync(0xffffffffu, den, o2);
    }
    if (j == 0) rowv[i] = -logf(num / den + EPSL);
    __syncthreads();
    if (tid == 0) {
        float s = 0.f;
        for (int r = 0; r < 32; r++) s += rowv[r];
        res[0] = s * (1.0f / 32.0f);
    }
}

// ---------------- kernel 6: NT-Xent + final scalar ----------------
__global__ void k_ntxent(const float* __restrict__ zs, const int* __restrict__ labels,
                         const float* __restrict__ infp, float* __restrict__ out) {
    __shared__ float s[32][257];     // padded for lane-varying row access
    __shared__ int lab[32];
    __shared__ float rowv[32];
    __shared__ float hasv[32];
    int tid = threadIdx.x;
    int i = tid >> 5, j = tid & 31;

    for (int idx = tid; idx < 32 * 256; idx += 1024) s[idx >> 8][idx & 255] = zs[idx];
    if (tid < 32) lab[tid] = labels[tid];
    __syncthreads();

    // normalize row i (warp per row, 8 elems per lane)
    {
        float ss = 0.f;
        #pragma unroll
        for (int t = 0; t < 8; t++) { float v = s[i][j + 32 * t]; ss += v * v; }
        #pragma unroll
        for (int o2 = 16; o2; o2 >>= 1) ss += __shfl_xor_sync(0xffffffffu, ss, o2);
        float inv = 1.0f / fmaxf(sqrtf(ss), 1e-12f);
        #pragma unroll
        for (int t = 0; t < 8; t++) s[i][j + 32 * t] *= inv;
    }
    __syncthreads();

    float d = 0.f;
    #pragma unroll 8
    for (int k = 0; k < 256; k++) d += s[i][k] * s[j][k];
    float e = expf(d * (1.0f / TEMP));
    bool same = (lab[i] == lab[j]);
    float maskv = (same && (i != j)) ? 1.0f : 0.0f;
    float pos = e * maskv;
    float neg = e * (1.0f - maskv);   // includes diagonal, per reference
    float cnt = maskv;
    #pragma unroll
    for (int o2 = 16; o2; o2 >>= 1) {
        pos += __shfl_xor_sync(0xffffffffu, pos, o2);
        neg += __shfl_xor_sync(0xffffffffu, neg, o2);
        cnt += __shfl_xor_sync(0xffffffffu, cnt, o2);
    }
    if (j == 0) {
        if (cnt > 0.f) {
            rowv[i] = -logf(pos / (pos + neg) + EPSL) / fmaxf(cnt, 1.0f);
            hasv[i] = 1.0f;
        } else {
            rowv[i] = 0.f;
            hasv[i] = 0.f;
        }
    }
    __syncthreads();
    if (tid == 0) {
        float sr = 0.f, sh = 0.f;
        for (int r = 0; r < 32; r++) { sr += rowv[r]; sh += hasv[r]; }
        float nt = sr / fmaxf(sh, 1.0f);
        out[0] = infp[0] + 0.5f * nt;   // LAMBDA_INFONCE=1, LAMBDA_NTXENT=0.5
    }
}

// ---------------- host launch ----------------
extern "C" void kernel_launch(void* const* d_in, const int* in_sizes, int n_in,
                              void* d_out, int out_size) {
    const float* span = (const float*)d_in[0];
    const float* la   = (const float*)d_in[1];
    const float* lo   = (const float*)d_in[2];
    const int*   lab  = (const int*)  d_in[3];
    const float* Wa1  = (const float*)d_in[4];
    const float* ba1  = (const float*)d_in[5];
    const float* Wa2  = (const float*)d_in[6];
    const float* ba2  = (const float*)d_in[7];
    const float* Wo1  = (const float*)d_in[8];
    const float* bo1  = (const float*)d_in[9];
    const float* Wo2  = (const float*)d_in[10];
    const float* bo2  = (const float*)d_in[11];
    const float* Ws1  = (const float*)d_in[12];
    const float* bs1  = (const float*)d_in[13];
    const float* Ws2  = (const float*)d_in[14];
    const float* bs2  = (const float*)d_in[15];
    float* out = (float*)d_out;

    float *p_wa, *p_wo, *p_pa, *p_po, *p_ae, *p_oe, *p_si, *p_gp;
    float *p_ha, *p_ho, *p_hs, *p_za, *p_zo, *p_zs, *p_if;
    cudaGetSymbolAddress((void**)&p_wa, g_wa);
    cudaGetSymbolAddress((void**)&p_wo, g_wo);
    cudaGetSymbolAddress((void**)&p_pa, g_pa);
    cudaGetSymbolAddress((void**)&p_po, g_po);
    cudaGetSymbolAddress((void**)&p_ae, g_aemb);
    cudaGetSymbolAddress((void**)&p_oe, g_oemb);
    cudaGetSymbolAddress((void**)&p_si, g_sin);
    cudaGetSymbolAddress((void**)&p_gp, g_gp);
    cudaGetSymbolAddress((void**)&p_ha, g_ha);
    cudaGetSymbolAddress((void**)&p_ho, g_ho);
    cudaGetSymbolAddress((void**)&p_hs, g_hs);
    cudaGetSymbolAddress((void**)&p_za, g_za);
    cudaGetSymbolAddress((void**)&p_zo, g_zo);
    cudaGetSymbolAddress((void**)&p_zs, g_zs);
    cudaGetSymbolAddress((void**)&p_if, g_inf);

    // 1. softmax pooling weights (aspect + opinion)
    k_softmax_w<<<dim3(32, 2), 256>>>(la, lo, p_wa, p_wo);

    // 2. pooled embeddings: one pass over the 256MB span tensor
    k_pool_partial<<<dim3(32, 32), 256>>>(span, p_wa, p_wo, p_pa, p_po);
    k_pool_reduce<<<128, 256>>>(p_pa, p_po, p_ae, p_oe, p_si);

    dim3 bt(32, 32);
    // 3. layer-1 GEMMs (relu)
    k_gemm_part<<<dim3(16, 4), bt>>>(p_ae, Wa1, p_gp, 1024, 512);
    k_gemm_combine<<<64, 256>>>(p_gp, ba1, p_ha, 512, 4, 1);
    k_gemm_part<<<dim3(16, 4), bt>>>(p_oe, Wo1, p_gp, 1024, 512);
    k_gemm_combine<<<64, 256>>>(p_gp, bo1, p_ho, 512, 4, 1);
    k_gemm_part<<<dim3(32, 8), bt>>>(p_si, Ws1, p_gp, 2048, 1024);
    k_gemm_combine<<<128, 256>>>(p_gp, bs1, p_hs, 1024, 8, 1);

    // 4. layer-2 GEMMs (bias only; l2norm happens in loss kernels)
    k_gemm_part<<<dim3(4, 2), bt>>>(p_ha, Wa2, p_gp, 512, 128);
    k_gemm_combine<<<16, 256>>>(p_gp, ba2, p_za, 128, 2, 0);
    k_gemm_part<<<dim3(4, 2), bt>>>(p_ho, Wo2, p_gp, 512, 128);
    k_gemm_combine<<<16, 256>>>(p_gp, bo2, p_zo, 128, 2, 0);
    k_gemm_part<<<dim3(8, 4), bt>>>(p_hs, Ws2, p_gp, 1024, 256);
    k_gemm_combine<<<32, 256>>>(p_gp, bs2, p_zs, 256, 4, 0);

    // 5. losses
    k_infonce<<<1, 1024>>>(p_za, p_zo, lab, p_if);
    k_ntxent<<<1, 1024>>>(p_zs, lab, p_if, out);
}

// round 3
// speedup vs baseline: 1.7415x; 1.7415x over previous
#include <cuda_runtime.h>
#include <cuda_bf16.h>
#include <math.h>

#define Bn 32
#define Sn 2048
#define Hn 1024
#define TEMP 0.07f
#define EPSL 1e-8f

// ---------------- device scratch (static, no allocation) ----------------
__device__ float g_wa[Bn * Sn];
__device__ float g_wo[Bn * Sn];
__device__ float g_pa[Bn * 32 * Hn];
__device__ float g_po[Bn * 32 * Hn];
__device__ float g_aemb[Bn * Hn];
__device__ float g_oemb[Bn * Hn];
__device__ float g_sin[Bn * 2 * Hn];
__device__ float g_gp[1572864];        // gemm partials: 3 regions (see offsets below)
__device__ float g_ha[Bn * 512];
__device__ float g_ho[Bn * 512];
__device__ float g_hs[Bn * 1024];
__device__ float g_za[Bn * 128];
__device__ float g_zo[Bn * 128];
__device__ float g_zs[Bn * 256];
__device__ float g_inf[1];

#define G0OFF 0
#define G1OFF 262144
#define G2OFF 524288

// ---------------- kernel 1: softmax weights over S ----------------
__global__ void k_softmax_w(const float* __restrict__ la,
                            const float* __restrict__ lo,
                            float* __restrict__ wa, float* __restrict__ wo) {
    int b = blockIdx.x;
    const float* L = blockIdx.y ? lo : la;
    float* W = blockIdx.y ? wo : wa;
    __shared__ float sc[Sn];
    __shared__ float red[16];
    int tid = threadIdx.x;           // 256 threads
    int lane = tid & 31, wid = tid >> 5;

    float m = -1e30f;
    for (int s = tid; s < Sn; s += 256) {
        const float* p = L + ((size_t)b * Sn + s) * 5;
        float v = p[1] + p[2] + p[3] + p[4];
        sc[s] = v;
        m = fmaxf(m, v);
    }
    #pragma unroll
    for (int o2 = 16; o2; o2 >>= 1) m = fmaxf(m, __shfl_xor_sync(0xffffffffu, m, o2));
    if (lane == 0) red[wid] = m;
    __syncthreads();
    if (tid == 0) {
        float mm = red[0];
        for (int w = 1; w < 8; w++) mm = fmaxf(mm, red[w]);
        red[8] = mm;
    }
    __syncthreads();
    m = red[8];
    __syncthreads();

    float sum = 0.f;
    for (int s = tid; s < Sn; s += 256) {
        float e = expf(sc[s] - m);
        sc[s] = e;
        sum += e;
    }
    #pragma unroll
    for (int o2 = 16; o2; o2 >>= 1) sum += __shfl_xor_sync(0xffffffffu, sum, o2);
    if (lane == 0) red[wid] = sum;
    __syncthreads();
    if (tid == 0) {
        float ss = 0.f;
        for (int w = 0; w < 8; w++) ss += red[w];
        red[9] = ss;
    }
    __syncthreads();
    float inv = 1.0f / red[9];
    for (int s = tid; s < Sn; s += 256) W[(size_t)b * Sn + s] = sc[s] * inv;
}

// ---------------- kernel 2: pooling partials (the 256MB pass) ----------------
__global__ void k_pool_partial(const float* __restrict__ span,
                               const float* __restrict__ wa,
                               const float* __restrict__ wo,
                               float* __restrict__ pa, float* __restrict__ po) {
    int sc = blockIdx.x, b = blockIdx.y;
    __shared__ float swa[64], swo[64];
    int tid = threadIdx.x;  // 256
    if (tid < 64) swa[tid] = wa[(size_t)b * Sn + sc * 64 + tid];
    else if (tid < 128) { int t = tid - 64; swo[t] = wo[(size_t)b * Sn + sc * 64 + t]; }
    __syncthreads();

    const float4* base = (const float4*)(span + ((size_t)b * Sn + (size_t)sc * 64) * Hn);
    float4 aa = make_float4(0.f, 0.f, 0.f, 0.f);
    float4 oo = make_float4(0.f, 0.f, 0.f, 0.f);
    #pragma unroll 8
    for (int s = 0; s < 64; s++) {
        float4 v = base[(size_t)s * 256 + tid];
        float fa = swa[s], fo = swo[s];
        aa.x += v.x * fa; aa.y += v.y * fa; aa.z += v.z * fa; aa.w += v.w * fa;
        oo.x += v.x * fo; oo.y += v.y * fo; oo.z += v.z * fo; oo.w += v.w * fo;
    }
    size_t off = ((size_t)b * 32 + sc) * Hn + tid * 4;
    *(float4*)(pa + off) = aa;
    *(float4*)(po + off) = oo;
}

// ---------------- kernel 3: reduce partials -> embeddings + concat ----------------
__global__ void k_pool_reduce(const float* __restrict__ pa, const float* __restrict__ po,
                              float* __restrict__ aemb, float* __restrict__ oemb,
                              float* __restrict__ sin_) {
    int idx = blockIdx.x * 256 + threadIdx.x;  // 32768 total
    int b = idx >> 10, h = idx & 1023;
    float sa = 0.f, so = 0.f;
    #pragma unroll 8
    for (int c = 0; c < 32; c++) {
        sa += pa[((size_t)b * 32 + c) * Hn + h];
        so += po[((size_t)b * 32 + c) * Hn + h];
    }
    aemb[idx] = sa;
    oemb[idx] = so;
    sin_[(size_t)b * 2048 + h] = sa;
    sin_[(size_t)b * 2048 + 1024 + h] = so;
}

// ---------------- kernel 4: fused MLP GEMM (3 gemms per launch) ----------------
// Each thread owns one output column j; accumulates all 32 batch rows in
// registers. One coalesced W load feeds 32 FMAs (x broadcast from smem).
// K split into 64-wide chunks -> partials, combined by k_combine.
struct GA { const float* x; const float* W; float* part; int K; int N; };

__global__ void __launch_bounds__(128) k_mlp_gemm(GA a0, GA a1, GA a2) {
    GA g = (blockIdx.z == 0) ? a0 : (blockIdx.z == 1 ? a1 : a2);
    int kc = g.K >> 6;            // number of 64-wide k-chunks
    int jt = g.N >> 7;            // number of 128-wide j-tiles
    if ((int)blockIdx.x >= kc * jt) return;
    int jtile = blockIdx.x % jt;
    int kch   = blockIdx.x / jt;
    int tid = threadIdx.x;        // 128
    int j = (jtile << 7) + tid;
    int k0 = kch << 6;

    __shared__ float xs[64][33];  // transposed x chunk: xs[k][b]
    for (int idx = tid; idx < 32 * 64; idx += 128) {
        int b = idx >> 6, kk = idx & 63;
        xs[kk][b] = g.x[(size_t)b * g.K + k0 + kk];
    }
    __syncthreads();

    float acc[32];
    #pragma unroll
    for (int b = 0; b < 32; b++) acc[b] = 0.f;

    const float* Wp = g.W + (size_t)k0 * g.N + j;
    #pragma unroll 4
    for (int k = 0; k < 64; k++) {
        float w = *Wp;
        Wp += g.N;
        #pragma unroll
        for (int b = 0; b < 32; b++) acc[b] += xs[k][b] * w;  // LDS broadcast
    }

    float* pp = g.part + (size_t)(kch * 32) * g.N + j;
    #pragma unroll
    for (int b = 0; b < 32; b++) pp[(size_t)b * g.N] = acc[b];
}

// ---------------- kernel 5: combine partials + bias (+relu), 3 segments ----------------
struct CA { const float* part; const float* bias; float* out; int N; int kc; };

__global__ void k_combine(CA c0, CA c1, CA c2, int relu) {
    int idx = blockIdx.x * 256 + threadIdx.x;
    int n0 = 32 * c0.N, n1 = 32 * c1.N, n2 = 32 * c2.N;
    CA c;
    int li;
    if (idx < n0) { c = c0; li = idx; }
    else if (idx < n0 + n1) { c = c1; li = idx - n0; }
    else if (idx < n0 + n1 + n2) { c = c2; li = idx - n0 - n1; }
    else return;
    int b = li / c.N, j = li % c.N;
    float s = c.bias[j];
    for (int ch = 0; ch < c.kc; ch++) s += c.part[(size_t)(ch * 32 + b) * c.N + j];
    if (relu) s = fmaxf(s, 0.f);
    c.out[li] = s;
}

// ---------------- kernel 6: InfoNCE (single block, 1024 threads) ----------------
__global__ void k_infonce(const float* __restrict__ za, const float* __restrict__ zo,
                          const int* __restrict__ labels, float* __restrict__ res) {
    __shared__ float a[32][128];
    __shared__ float o[32][129];
    __shared__ int lab[32];
    __shared__ float rowv[32];
    int tid = threadIdx.x;
    int i = tid >> 5, j = tid & 31;

    for (int idx = tid; idx < 32 * 128; idx += 1024) a[idx >> 7][idx & 127] = za[idx];
    for (int idx = tid; idx < 32 * 128; idx += 1024) o[idx >> 7][idx & 127] = zo[idx];
    if (tid < 32) lab[tid] = labels[tid];
    __syncthreads();

    {
        float sa = 0.f, so = 0.f;
        #pragma unroll
        for (int t = 0; t < 4; t++) {
            float va = a[i][j + 32 * t]; sa += va * va;
            float vo = o[i][j + 32 * t]; so += vo * vo;
        }
        #pragma unroll
        for (int o2 = 16; o2; o2 >>= 1) {
            sa += __shfl_xor_sync(0xffffffffu, sa, o2);
            so += __shfl_xor_sync(0xffffffffu, so, o2);
        }
        float ia = 1.0f / fmaxf(sqrtf(sa), 1e-12f);
        float io = 1.0f / fmaxf(sqrtf(so), 1e-12f);
        #pragma unroll
        for (int t = 0; t < 4; t++) {
            a[i][j + 32 * t] *= ia;
            o[i][j + 32 * t] *= io;
        }
    }
    __syncthreads();

    float d = 0.f;
    #pragma unroll 8
    for (int k = 0; k < 128; k++) d += a[i][k] * o[j][k];
    float e = expf(d * (1.0f / TEMP));
    bool same = (lab[i] == lab[j]);
    float pm = (i == j) ? 1.0f : (same ? 0.5f : 0.0f);
    float num = e * pm, den = e;
    #pragma unroll
    for (int o2 = 16; o2; o2 >>= 1) {
        num += __shfl_xor_sync(0xffffffffu, num, o2);
        den += __shfl_xor_sync(0xffffffffu, den, o2);
    }
    if (j == 0) rowv[i] = -logf(num / den + EPSL);
    __syncthreads();
    if (tid == 0) {
        float s = 0.f;
        for (int r = 0; r < 32; r++) s += rowv[r];
        res[0] = s * (1.0f / 32.0f);
    }
}

// ---------------- kernel 7: NT-Xent + final scalar ----------------
__global__ void k_ntxent(const float* __restrict__ zs, const int* __restrict__ labels,
                         const float* __restrict__ infp, float* __restrict__ out) {
    __shared__ float s[32][257];
    __shared__ int lab[32];
    __shared__ float rowv[32];
    __shared__ float hasv[32];
    int tid = threadIdx.x;
    int i = tid >> 5, j = tid & 31;

    for (int idx = tid; idx < 32 * 256; idx += 1024) s[idx >> 8][idx & 255] = zs[idx];
    if (tid < 32) lab[tid] = labels[tid];
    __syncthreads();

    {
        float ss = 0.f;
        #pragma unroll
        for (int t = 0; t < 8; t++) { float v = s[i][j + 32 * t]; ss += v * v; }
        #pragma unroll
        for (int o2 = 16; o2; o2 >>= 1) ss += __shfl_xor_sync(0xffffffffu, ss, o2);
        float inv = 1.0f / fmaxf(sqrtf(ss), 1e-12f);
        #pragma unroll
        for (int t = 0; t < 8; t++) s[i][j + 32 * t] *= inv;
    }
    __syncthreads();

    float d = 0.f;
    #pragma unroll 8
    for (int k = 0; k < 256; k++) d += s[i][k] * s[j][k];
    float e = expf(d * (1.0f / TEMP));
    bool same = (lab[i] == lab[j]);
    float maskv = (same && (i != j)) ? 1.0f : 0.0f;
    float pos = e * maskv;
    float neg = e * (1.0f - maskv);
    float cnt = maskv;
    #pragma unroll
    for (int o2 = 16; o2; o2 >>= 1) {
        pos += __shfl_xor_sync(0xffffffffu, pos, o2);
        neg += __shfl_xor_sync(0xffffffffu, neg, o2);
        cnt += __shfl_xor_sync(0xffffffffu, cnt, o2);
    }
    if (j == 0) {
        if (cnt > 0.f) {
            rowv[i] = -logf(pos / (pos + neg) + EPSL) / fmaxf(cnt, 1.0f);
            hasv[i] = 1.0f;
        } else {
            rowv[i] = 0.f;
            hasv[i] = 0.f;
        }
    }
    __syncthreads();
    if (tid == 0) {
        float sr = 0.f, sh = 0.f;
        for (int r = 0; r < 32; r++) { sr += rowv[r]; sh += hasv[r]; }
        float nt = sr / fmaxf(sh, 1.0f);
        out[0] = infp[0] + 0.5f * nt;
    }
}

// ---------------- host launch ----------------
extern "C" void kernel_launch(void* const* d_in, const int* in_sizes, int n_in,
                              void* d_out, int out_size) {
    const float* span = (const float*)d_in[0];
    const float* la   = (const float*)d_in[1];
    const float* lo   = (const float*)d_in[2];
    const int*   lab  = (const int*)  d_in[3];
    const float* Wa1  = (const float*)d_in[4];
    const float* ba1  = (const float*)d_in[5];
    const float* Wa2  = (const float*)d_in[6];
    const float* ba2  = (const float*)d_in[7];
    const float* Wo1  = (const float*)d_in[8];
    const float* bo1  = (const float*)d_in[9];
    const float* Wo2  = (const float*)d_in[10];
    const float* bo2  = (const float*)d_in[11];
    const float* Ws1  = (const float*)d_in[12];
    const float* bs1  = (const float*)d_in[13];
    const float* Ws2  = (const float*)d_in[14];
    const float* bs2  = (const float*)d_in[15];
    float* out = (float*)d_out;

    float *p_wa, *p_wo, *p_pa, *p_po, *p_ae, *p_oe, *p_si, *p_gp;
    float *p_ha, *p_ho, *p_hs, *p_za, *p_zo, *p_zs, *p_if;
    cudaGetSymbolAddress((void**)&p_wa, g_wa);
    cudaGetSymbolAddress((void**)&p_wo, g_wo);
    cudaGetSymbolAddress((void**)&p_pa, g_pa);
    cudaGetSymbolAddress((void**)&p_po, g_po);
    cudaGetSymbolAddress((void**)&p_ae, g_aemb);
    cudaGetSymbolAddress((void**)&p_oe, g_oemb);
    cudaGetSymbolAddress((void**)&p_si, g_sin);
    cudaGetSymbolAddress((void**)&p_gp, g_gp);
    cudaGetSymbolAddress((void**)&p_ha, g_ha);
    cudaGetSymbolAddress((void**)&p_ho, g_ho);
    cudaGetSymbolAddress((void**)&p_hs, g_hs);
    cudaGetSymbolAddress((void**)&p_za, g_za);
    cudaGetSymbolAddress((void**)&p_zo, g_zo);
    cudaGetSymbolAddress((void**)&p_zs, g_zs);
    cudaGetSymbolAddress((void**)&p_if, g_inf);

    // 1. softmax pooling weights
    k_softmax_w<<<dim3(32, 2), 256>>>(la, lo, p_wa, p_wo);

    // 2. pooled embeddings: one pass over the 256MB span tensor
    k_pool_partial<<<dim3(32, 32), 256>>>(span, p_wa, p_wo, p_pa, p_po);
    k_pool_reduce<<<128, 256>>>(p_pa, p_po, p_ae, p_oe, p_si);

    // 3. layer-1 GEMMs in one launch (relu in combine)
    {
        GA a0 = {p_ae, Wa1, p_gp + G0OFF, 1024, 512};
        GA a1 = {p_oe, Wo1, p_gp + G1OFF, 1024, 512};
        GA a2 = {p_si, Ws1, p_gp + G2OFF, 2048, 1024};
        k_mlp_gemm<<<dim3(256, 1, 3), 128>>>(a0, a1, a2);
        CA c0 = {p_gp + G0OFF, ba1, p_ha, 512, 16};
        CA c1 = {p_gp + G1OFF, bo1, p_ho, 512, 16};
        CA c2 = {p_gp + G2OFF, bs1, p_hs, 1024, 32};
        k_combine<<<256, 256>>>(c0, c1, c2, 1);
    }

    // 4. layer-2 GEMMs in one launch (bias only)
    {
        GA a0 = {p_ha, Wa2, p_gp + G0OFF, 512, 128};
        GA a1 = {p_ho, Wo2, p_gp + G1OFF, 512, 128};
        GA a2 = {p_hs, Ws2, p_gp + G2OFF, 1024, 256};
        k_mlp_gemm<<<dim3(32, 1, 3), 128>>>(a0, a1, a2);
        CA c0 = {p_gp + G0OFF, ba2, p_za, 128, 8};
        CA c1 = {p_gp + G1OFF, bo2, p_zo, 128, 8};
        CA c2 = {p_gp + G2OFF, bs2, p_zs, 256, 16};
        k_combine<<<64, 256>>>(c0, c1, c2, 0);
    }

    // 5. losses
    k_infonce<<<1, 1024>>>(p_za, p_zo, lab, p_if);
    k_ntxent<<<1, 1024>>>(p_zs, lab, p_if, out);
}